// round 13
// baseline (speedup 1.0000x reference)
#include <cuda_runtime.h>

// Shapes fixed by the problem: x,f = (B=2, 3, T=5, H=720, W=1280) fp32.
// Output = concat(ow, xw), each (B,3,T,H,W) fp32.
constexpr unsigned B  = 2;
constexpr unsigned C  = 3;
constexpr unsigned T  = 5;
constexpr unsigned H  = 720;
constexpr unsigned W  = 1280;
constexpr unsigned PLANE = H * W;            // 921,600
constexpr unsigned CH    = T * PLANE;        // 4,608,000
constexpr unsigned HALF  = B * C * CH;       // 27,648,000

// 1 px/thread: warp lanes cover 32 consecutive w -> gather LDG footprint is
// ~128B per touched image row (vs 512B at 2px/thread) -> ~2.5x fewer L1tex
// wavefronts per gather. f loads / stores go scalar but stay 1-wf coalesced.
// grid: x -> 10 segments of 128 px, y -> 360 pairs of rows, z -> (b,t)
// block: (128, 2) = 256 threads.

__global__ __launch_bounds__(256)
void ImageBWarp_65343632441725_kernel(const float* __restrict__ x,
                                      const float* __restrict__ f,
                                      float* __restrict__ out)
{
    // zero-division index decode
    unsigned w  = blockIdx.x * 128u + threadIdx.x;
    unsigned h  = blockIdx.y * 2u + threadIdx.y;
    unsigned bt = blockIdx.z;                 // b*T + t
    unsigned b  = bt / T;
    unsigned base = (bt + b * ((C - 1) * T)) * PLANE;   // (b*C*T + t)*PLANE
    unsigned hw   = h * W + w;

    const float* fb = f + base + hw;
    float fx = __ldg(fb);
    float fy = __ldg(fb + CH);
    float wl = __ldg(fb + 2u * CH);

    float gx = (float)w + fx;
    float gy = (float)h + fy;

    float x0f = floorf(gx);
    float y0f = floorf(gy);
    float wx1 = gx - x0f;
    float wy1 = gy - y0f;
    float wx0 = 1.0f - wx1;
    float wy0 = 1.0f - wy1;

    int ix0 = (int)x0f;
    int iy0 = (int)y0f;
    int ix1 = ix0 + 1;
    int iy1 = iy0 + 1;

    bool vx0 = (unsigned)ix0 < W;
    bool vx1 = (unsigned)ix1 < W;
    bool vy0 = (unsigned)iy0 < H;
    bool vy1 = (unsigned)iy1 < H;

    float m00 = (vx0 && vy0) ? wx0 * wy0 : 0.0f;
    float m10 = (vx1 && vy0) ? wx1 * wy0 : 0.0f;
    float m01 = (vx0 && vy1) ? wx0 * wy1 : 0.0f;
    float m11 = (vx1 && vy1) ? wx1 * wy1 : 0.0f;

    unsigned cx0 = (unsigned)min(max(ix0, 0), (int)W - 1);
    unsigned cx1 = (unsigned)min(max(ix1, 0), (int)W - 1);
    unsigned cy0 = (unsigned)min(max(iy0, 0), (int)H - 1);
    unsigned cy1 = (unsigned)min(max(iy1, 0), (int)H - 1);

    unsigned o00 = cy0 * W + cx0;
    unsigned o10 = cy0 * W + cx1;
    unsigned o01 = cy1 * W + cx0;
    unsigned o11 = cy1 * W + cx1;

    // sigmoid via HW tanh: sigmoid(x) = 0.5*tanh(x/2) + 0.5
    float wgt = 0.5f * __tanhf(0.5f * wl) + 0.5f;
    float owv = wgt * (m00 + m10 + m01 + m11);

    // store the 3 identical ow planes first (overlaps gather latency)
    float* out_ow = out + base + hw;
    out_ow[0]       = owv;
    out_ow[CH]      = owv;
    out_ow[2u * CH] = owv;

    float*       out_xw = out_ow + HALF;
    const float* xb     = x + base;

#pragma unroll
    for (unsigned c = 0; c < C; c++) {
        const float* xc = xb + c * CH;
        float v00 = __ldg(xc + o00);
        float v10 = __ldg(xc + o10);
        float v01 = __ldg(xc + o01);
        float v11 = __ldg(xc + o11);

        float s = m00 * v00 + m10 * v10 + m01 * v01 + m11 * v11;
        out_xw[c * CH] = s * wgt;
    }
}

extern "C" void kernel_launch(void* const* d_in, const int* in_sizes, int n_in,
                              void* d_out, int out_size)
{
    const float* x = (const float*)d_in[0];
    const float* f = (const float*)d_in[1];
    float* out = (float*)d_out;

    dim3 block(128, 2, 1);
    dim3 grid(W / 128, H / 2, B * T);   // (10, 360, 10)
    ImageBWarp_65343632441725_kernel<<<grid, block>>>(x, f, out);
}

// round 14
// speedup vs baseline: 1.1150x; 1.1150x over previous
#include <cuda_runtime.h>

// Shapes fixed by the problem: x,f = (B=2, 3, T=5, H=720, W=1280) fp32.
// Output = concat(ow, xw), each (B,3,T,H,W) fp32.
//
// R7 shape (2 px/thread, 32 regs, tanh sigmoid, early ow stores, 8-load
// batches) with 1024-thread CTAs: 2 CTAs/SM instead of 8 -> the SM's L1
// holds 2 gather working sets instead of 8 -> higher L1 hit rate on the
// 4x-overlapping bilinear taps.
constexpr unsigned B  = 2;
constexpr unsigned C  = 3;
constexpr unsigned T  = 5;
constexpr unsigned H  = 720;
constexpr unsigned W  = 1280;
constexpr unsigned PLANE = H * W;            // 921,600
constexpr unsigned CH    = T * PLANE;        // 4,608,000
constexpr unsigned HALF  = B * C * CH;       // 27,648,000

// grid: x -> 5 segments of 256 px, y -> 90 groups of 8 rows, z -> (b,t)
// block: (128, 8) = 1024 threads, each thread 2 horizontally adjacent px.

__global__ __launch_bounds__(1024)
void ImageBWarp_65343632441725_kernel(const float* __restrict__ x,
                                      const float* __restrict__ f,
                                      float* __restrict__ out)
{
    // zero-division index decode
    unsigned w0 = (blockIdx.x * 128u + threadIdx.x) * 2u;
    unsigned h  = blockIdx.y * 8u + threadIdx.y;
    unsigned bt = blockIdx.z;                 // b*T + t
    unsigned b  = bt / T;
    unsigned base = (bt + b * ((C - 1) * T)) * PLANE;   // (b*C*T + t)*PLANE
    unsigned hw   = h * W + w0;               // 8B-aligned

    const float2 fx2 = *(const float2*)(f + base + hw);
    const float2 fy2 = *(const float2*)(f + base + CH + hw);
    const float2 wl2 = *(const float2*)(f + base + 2u * CH + hw);

    float fx[2] = {fx2.x, fx2.y};
    float fy[2] = {fy2.x, fy2.y};
    float wl[2] = {wl2.x, wl2.y};

    float m00[2], m10[2], m01[2], m11[2];
    unsigned o00[2], o10[2], o01[2], o11[2];
    float wgt[2], owv[2];

#pragma unroll
    for (int j = 0; j < 2; j++) {
        float gx = (float)(w0 + (unsigned)j) + fx[j];
        float gy = (float)h + fy[j];

        float x0f = floorf(gx);
        float y0f = floorf(gy);
        float wx1 = gx - x0f;
        float wy1 = gy - y0f;
        float wx0 = 1.0f - wx1;
        float wy0 = 1.0f - wy1;

        int ix0 = (int)x0f;
        int iy0 = (int)y0f;
        int ix1 = ix0 + 1;
        int iy1 = iy0 + 1;

        bool vx0 = (unsigned)ix0 < W;
        bool vx1 = (unsigned)ix1 < W;
        bool vy0 = (unsigned)iy0 < H;
        bool vy1 = (unsigned)iy1 < H;

        m00[j] = (vx0 && vy0) ? wx0 * wy0 : 0.0f;
        m10[j] = (vx1 && vy0) ? wx1 * wy0 : 0.0f;
        m01[j] = (vx0 && vy1) ? wx0 * wy1 : 0.0f;
        m11[j] = (vx1 && vy1) ? wx1 * wy1 : 0.0f;

        unsigned cx0 = (unsigned)min(max(ix0, 0), (int)W - 1);
        unsigned cx1 = (unsigned)min(max(ix1, 0), (int)W - 1);
        unsigned cy0 = (unsigned)min(max(iy0, 0), (int)H - 1);
        unsigned cy1 = (unsigned)min(max(iy1, 0), (int)H - 1);

        o00[j] = cy0 * W + cx0;
        o10[j] = cy0 * W + cx1;
        o01[j] = cy1 * W + cx0;
        o11[j] = cy1 * W + cx1;

        // sigmoid via HW tanh: sigmoid(x) = 0.5*tanh(x/2) + 0.5
        wgt[j] = 0.5f * __tanhf(0.5f * wl[j]) + 0.5f;
        owv[j] = wgt[j] * (m00[j] + m10[j] + m01[j] + m11[j]);
    }

    // store the 3 identical ow planes first: overlaps with gather latency,
    // frees owv registers before the gather loop
    float* out_ow = out + base + hw;
    {
        float2 ow2 = make_float2(owv[0], owv[1]);
        *(float2*)(out_ow)           = ow2;
        *(float2*)(out_ow + CH)      = ow2;
        *(float2*)(out_ow + 2u * CH) = ow2;
    }

    float*       out_xw = out_ow + HALF;
    const float* xb     = x + base;

#pragma unroll
    for (unsigned c = 0; c < C; c++) {
        const float* xc = xb + c * CH;
        float v00a = __ldg(xc + o00[0]);
        float v10a = __ldg(xc + o10[0]);
        float v01a = __ldg(xc + o01[0]);
        float v11a = __ldg(xc + o11[0]);
        float v00b = __ldg(xc + o00[1]);
        float v10b = __ldg(xc + o10[1]);
        float v01b = __ldg(xc + o01[1]);
        float v11b = __ldg(xc + o11[1]);

        float sa = m00[0] * v00a + m10[0] * v10a + m01[0] * v01a + m11[0] * v11a;
        float sb = m00[1] * v00b + m10[1] * v10b + m01[1] * v01b + m11[1] * v11b;

        *(float2*)(out_xw + c * CH) = make_float2(sa * wgt[0], sb * wgt[1]);
    }
}

extern "C" void kernel_launch(void* const* d_in, const int* in_sizes, int n_in,
                              void* d_out, int out_size)
{
    const float* x = (const float*)d_in[0];
    const float* f = (const float*)d_in[1];
    float* out = (float*)d_out;

    dim3 block(128, 8, 1);
    dim3 grid(W / 256, H / 8, B * T);   // (5, 90, 10)
    ImageBWarp_65343632441725_kernel<<<grid, block>>>(x, f, out);
}